// round 1
// baseline (speedup 1.0000x reference)
#include <cuda_runtime.h>
#include <cstdint>

// Problem constants
#define BDIM 128     // batch
#define TDIM 512     // timesteps
#define HDIM 1024    // hidden
#define G4   4096    // 4*H gate rows
#define ODIM 128     // output

typedef unsigned long long ull;

// ---------------- device scratch (no allocations allowed) ----------------
__device__ float g_hbuf[2][HDIM * BDIM];         // h state, k-major: [k][b], double buffered (1 MB)
__device__ float g_W2[HDIM * HDIM * 4];          // W_hh transposed+interleaved: [k][j][gate] (16 MB)
__device__ float g_bsum[G4];                     // b_ih + b_hh
__device__ unsigned g_arrive;                    // grid barrier arrive counter
__device__ volatile unsigned g_release;          // grid barrier release (monotonic step count)

// ---------------- f32x2 packed-FMA helpers (FFMA2, sm_10x) ----------------
__device__ __forceinline__ ull pack2(float a, float b) {
    ull r; asm("mov.b64 %0, {%1, %2};" : "=l"(r) : "f"(a), "f"(b)); return r;
}
__device__ __forceinline__ void unpack2(ull v, float& a, float& b) {
    asm("mov.b64 {%0, %1}, %2;" : "=f"(a), "=f"(b) : "l"(v));
}
__device__ __forceinline__ void ffma2(ull& d, ull a, ull b) {
    asm("fma.rn.f32x2 %0, %1, %2, %0;" : "+l"(d) : "l"(a), "l"(b));
}
__device__ __forceinline__ float sigmoidf_(float x) {
    return 1.0f / (1.0f + __expf(-x));
}

// ---------------- prep kernels (run every launch; deterministic) ----------------
// W2[k*4096 + j*4 + g] = W_hh[(g*1024 + j)*1024 + k]
__global__ void prep_w2(const float* __restrict__ W_hh) {
    int idx = blockIdx.x * blockDim.x + threadIdx.x;
    if (idx < HDIM * HDIM * 4) {
        int g = idx & 3;
        int j = (idx >> 2) & (HDIM - 1);
        int k = idx >> 12;
        g_W2[idx] = W_hh[((g << 10) + j) * HDIM + k];
    }
}

// bsum, h0 transpose (to k-major), barrier reset
__global__ void prep_misc(const float* __restrict__ b_ih,
                          const float* __restrict__ b_hh,
                          const float* __restrict__ h0) {
    int idx = blockIdx.x * blockDim.x + threadIdx.x;
    if (idx < G4) g_bsum[idx] = b_ih[idx] + b_hh[idx];
    if (idx < BDIM * HDIM) {
        int b = idx >> 10;           // row of h0
        int k = idx & (HDIM - 1);    // col of h0
        g_hbuf[0][k * BDIM + b] = h0[idx];
    }
    if (idx == 0) { g_arrive = 0u; g_release = 0u; }
}

// ---------------- grid-wide barrier ----------------
// Monotonic-release barrier. All 128 CTAs are trivially co-resident (no smem,
// ~50 regs, 256 threads). __threadfence() at gpu scope emits CCTL.IVALL on
// sm_103a, invalidating stale L1 lines of the h buffers.
__device__ __forceinline__ void grid_barrier(unsigned want, unsigned nblk) {
    __syncthreads();
    if (threadIdx.x == 0) {
        __threadfence();  // publish this CTA's h writes
        unsigned t = atomicAdd(&g_arrive, 1u);
        if (t == nblk - 1u) {
            atomicExch(&g_arrive, 0u);
            __threadfence();
            g_release = want;
        } else {
            while (g_release < want) { }
            __threadfence();  // acquire + L1 invalidate
        }
    }
    __syncthreads();
}

// ---------------- persistent LSTM kernel ----------------
// Grid: 128 blocks = 4 batch-groups x 32 j-groups. Block: 256 threads = 8 warps.
// Warp w covers batches [bg*32 + w*4, +4), lanes cover 32 consecutive j.
// Each thread owns 4 (b,j) cells: c lives in registers for the whole run.
__global__ void __launch_bounds__(256, 1)
lstm_persistent(const float* __restrict__ y_hist,   // [B][T]
                const float* __restrict__ W_ih,     // [4096] (x1 col)
                const float* __restrict__ c0)       // [B][H]
{
    const int lane = threadIdx.x & 31;
    const int warp = threadIdx.x >> 5;
    const int jb   = blockIdx.x & 31;   // j-group
    const int bg   = blockIdx.x >> 5;   // batch-group
    const int j    = jb * 32 + lane;    // hidden index this thread computes
    const int b0   = bg * 32 + warp * 4;  // first of 4 batches
    const unsigned nblk = gridDim.x;

    // per-thread constants
    float wih[4], bs[4];
#pragma unroll
    for (int g = 0; g < 4; g++) {
        wih[g] = W_ih[(g << 10) + j];
        bs[g]  = g_bsum[(g << 10) + j];
    }
    // c state in registers
    float creg[4];
#pragma unroll
    for (int i = 0; i < 4; i++) creg[i] = c0[(b0 + i) * HDIM + j];

    const float4* wp = reinterpret_cast<const float4*>(g_W2) + j;  // + k*1024 per k

    for (int t = 0; t < TDIM; t++) {
        const float* hcur = g_hbuf[t & 1];
        float*       hnxt = g_hbuf[(t + 1) & 1];

        // x_t and accumulator init: acc = x*w_ih + (b_ih+b_hh)
        float x0 = y_hist[(b0 + 0) * TDIM + t];
        float x1 = y_hist[(b0 + 1) * TDIM + t];
        float x2 = y_hist[(b0 + 2) * TDIM + t];
        float x3 = y_hist[(b0 + 3) * TDIM + t];

        ull acc[4][2];
#pragma unroll
        for (int g = 0; g < 4; g++) {
            acc[g][0] = pack2(fmaf(x0, wih[g], bs[g]), fmaf(x1, wih[g], bs[g]));
            acc[g][1] = pack2(fmaf(x2, wih[g], bs[g]), fmaf(x3, wih[g], bs[g]));
        }

        const float4* hp = reinterpret_cast<const float4*>(hcur) + (b0 >> 2);  // + k*32 per k

#pragma unroll 4
        for (int k = 0; k < HDIM; k++) {
            float4 hv = __ldcg(hp + k * (BDIM / 4));   // 4 batches at col k (L2 path: coherent)
            float4 wq = __ldg(wp + k * HDIM);          // 4 gate weights for (k, j)
            ull h01 = pack2(hv.x, hv.y);
            ull h23 = pack2(hv.z, hv.w);
            ull wb;
            wb = pack2(wq.x, wq.x); ffma2(acc[0][0], h01, wb); ffma2(acc[0][1], h23, wb);
            wb = pack2(wq.y, wq.y); ffma2(acc[1][0], h01, wb); ffma2(acc[1][1], h23, wb);
            wb = pack2(wq.z, wq.z); ffma2(acc[2][0], h01, wb); ffma2(acc[2][1], h23, wb);
            wb = pack2(wq.w, wq.w); ffma2(acc[3][0], h01, wb); ffma2(acc[3][1], h23, wb);
        }

        // gate nonlinearities + state update for the 4 owned batches
        float iv[4], fv[4], gv[4], ov[4];
        unpack2(acc[0][0], iv[0], iv[1]); unpack2(acc[0][1], iv[2], iv[3]);
        unpack2(acc[1][0], fv[0], fv[1]); unpack2(acc[1][1], fv[2], fv[3]);
        unpack2(acc[2][0], gv[0], gv[1]); unpack2(acc[2][1], gv[2], gv[3]);
        unpack2(acc[3][0], ov[0], ov[1]); unpack2(acc[3][1], ov[2], ov[3]);

        float hn[4];
#pragma unroll
        for (int i = 0; i < 4; i++) {
            float ig = sigmoidf_(iv[i]);
            float fg = sigmoidf_(fv[i]);
            float gg = tanhf(gv[i]);
            float og = sigmoidf_(ov[i]);
            creg[i] = fg * creg[i] + ig * gg;
            hn[i]   = og * tanhf(creg[i]);
        }
        reinterpret_cast<float4*>(hnxt)[j * (BDIM / 4) + (b0 >> 2)] =
            make_float4(hn[0], hn[1], hn[2], hn[3]);

        grid_barrier((unsigned)(t + 1), nblk);
    }
    // final h lands in g_hbuf[0] (512 is even)
}

// ---------------- final FC: out[b][o] = h_T[b] . fc_W[o] + fc_b[o] ----------------
__global__ void fc_kernel(const float* __restrict__ fc_W,
                          const float* __restrict__ fc_b,
                          float* __restrict__ out) {
    int b = blockIdx.x;
    int o = threadIdx.x;
    const float* h = g_hbuf[0];   // k-major [k][b]
    const float4* wp = reinterpret_cast<const float4*>(fc_W + o * HDIM);
    float s = 0.0f;
#pragma unroll 4
    for (int k = 0; k < HDIM; k += 4) {
        float4 w = wp[k >> 2];
        s += h[(k + 0) * BDIM + b] * w.x;
        s += h[(k + 1) * BDIM + b] * w.y;
        s += h[(k + 2) * BDIM + b] * w.z;
        s += h[(k + 3) * BDIM + b] * w.w;
    }
    out[b * ODIM + o] = s + fc_b[o];
}

// ---------------- launch ----------------
extern "C" void kernel_launch(void* const* d_in, const int* in_sizes, int n_in,
                              void* d_out, int out_size) {
    const float* y_hist = (const float*)d_in[0];  // (128, 512)
    const float* W_ih   = (const float*)d_in[1];  // (4096, 1)
    const float* W_hh   = (const float*)d_in[2];  // (4096, 1024)
    const float* b_ih   = (const float*)d_in[3];  // (4096,)
    const float* b_hh   = (const float*)d_in[4];  // (4096,)
    const float* fc_W   = (const float*)d_in[5];  // (128, 1024)
    const float* fc_b   = (const float*)d_in[6];  // (128,)
    const float* h0     = (const float*)d_in[7];  // (128, 1024)
    const float* c0     = (const float*)d_in[8];  // (128, 1024)
    float* out = (float*)d_out;                   // (128, 128)

    prep_w2<<<(HDIM * HDIM * 4 + 255) / 256, 256>>>(W_hh);
    prep_misc<<<(BDIM * HDIM + 255) / 256, 256>>>(b_ih, b_hh, h0);
    lstm_persistent<<<128, 256>>>(y_hist, W_ih, c0);
    fc_kernel<<<BDIM, ODIM>>>(fc_W, fc_b, out);
}

// round 3
// speedup vs baseline: 1.3812x; 1.3812x over previous
#include <cuda_runtime.h>
#include <cstdint>

// Problem constants
#define BDIM 128     // batch
#define TDIM 512     // timesteps
#define HDIM 1024    // hidden
#define G4   4096    // 4*H gate rows
#define ODIM 128     // output
#define KHALF 512    // k-phase size (h smem staged in 2 halves)

typedef unsigned long long ull;

// ---------------- device scratch (no allocations allowed) ----------------
__device__ float g_hbuf[2][HDIM * BDIM];   // h state, k-major: [k][b], double buffered
__device__ float g_W2[HDIM * HDIM * 4];    // W_hh transposed: [k][j][gate(i,f,g,o)]
__device__ float g_bsum[G4];               // b_ih + b_hh
__device__ unsigned g_arrive;
__device__ volatile unsigned g_release;

// ---------------- f32x2 packed-FMA helpers (FFMA2, sm_10x) ----------------
__device__ __forceinline__ ull pack2(float a, float b) {
    ull r; asm("mov.b64 %0, {%1, %2};" : "=l"(r) : "f"(a), "f"(b)); return r;
}
__device__ __forceinline__ void unpack2(ull v, float& a, float& b) {
    asm("mov.b64 {%0, %1}, %2;" : "=f"(a), "=f"(b) : "l"(v));
}
__device__ __forceinline__ void ffma2(ull& d, ull a, ull b) {
    asm("fma.rn.f32x2 %0, %1, %2, %0;" : "+l"(d) : "l"(a), "l"(b));
}
__device__ __forceinline__ float sigmoidf_(float x) {
    return 1.0f / (1.0f + __expf(-x));
}

// ---------------- prep kernels ----------------
// W2[k*4096 + j*4 + g] = W_hh[(g*1024 + j)*1024 + k]
__global__ void prep_w2(const float* __restrict__ W_hh) {
    int idx = blockIdx.x * blockDim.x + threadIdx.x;
    if (idx < HDIM * HDIM * 4) {
        int g = idx & 3;
        int j = (idx >> 2) & (HDIM - 1);
        int k = idx >> 12;
        g_W2[idx] = W_hh[((g << 10) + j) * HDIM + k];
    }
}

__global__ void prep_misc(const float* __restrict__ b_ih,
                          const float* __restrict__ b_hh,
                          const float* __restrict__ h0) {
    int idx = blockIdx.x * blockDim.x + threadIdx.x;
    if (idx < G4) g_bsum[idx] = b_ih[idx] + b_hh[idx];
    if (idx < BDIM * HDIM) {
        int b = idx >> 10;
        int k = idx & (HDIM - 1);
        g_hbuf[0][k * BDIM + b] = h0[idx];
    }
    if (idx == 0) { g_arrive = 0u; g_release = 0u; }
}

// ---------------- grid-wide barrier (monotonic release) ----------------
// All 128 CTAs co-resident (128 KB smem, 512 thr, occupancy 1/SM on 148 SMs).
__device__ __forceinline__ void grid_barrier(unsigned want, unsigned nblk) {
    __syncthreads();
    if (threadIdx.x == 0) {
        __threadfence();  // publish h writes (CCTL.IVALL at gpu scope)
        unsigned t = atomicAdd(&g_arrive, 1u);
        if (t == nblk - 1u) {
            atomicExch(&g_arrive, 0u);
            __threadfence();
            g_release = want;
        } else {
            while (g_release < want) { }
            __threadfence();  // acquire + L1 invalidate
        }
    }
    __syncthreads();
}

// ---------------- persistent LSTM kernel ----------------
// Grid 128 = 32 j-groups x 4 batch-groups. Block 512 = 16 warps (4/SMSP).
// Warp w: batches (bg*32 + w*2, +1). Lane: j = jb*32 + lane.
// Accumulator lanes are GATE pairs (i,f)/(g,o): the W float4 [k][j][4] is
// consumed directly as two f32x2 operands — no broadcast MOVs.
// h is staged in smem pre-duplicated (h_b,h_b), in two 512-k phases (128 KB).
__global__ void __launch_bounds__(512, 1)
lstm_persistent(const float* __restrict__ y_hist,   // [B][T]
                const float* __restrict__ W_ih,     // [4096]
                const float* __restrict__ c0)       // [B][H]
{
    extern __shared__ float h_s[];   // [KHALF][32 batches][2 dup] = 128 KB

    const int tid  = threadIdx.x;
    const int lane = tid & 31;
    const int warp = tid >> 5;
    const int jb   = blockIdx.x & 31;
    const int bg   = blockIdx.x >> 5;
    const int j    = jb * 32 + lane;
    const int b0   = bg * 32 + warp * 2;   // this thread's two batches
    const int bloc = warp * 2;             // local batch index in [0,32)
    const unsigned nblk = gridDim.x;

    float wih_[4], bs_[4];
#pragma unroll
    for (int g = 0; g < 4; g++) {
        wih_[g] = W_ih[(g << 10) + j];
        bs_[g]  = g_bsum[(g << 10) + j];
    }
    float c_[2];
    c_[0] = c0[(b0 + 0) * HDIM + j];
    c_[1] = c0[(b0 + 1) * HDIM + j];

    // W row pointer: longlong2 per (k,j) = {(w_i,w_f),(w_g,w_o)}
    const longlong2* wbase = reinterpret_cast<const longlong2*>(g_W2) + j;

    for (int t = 0; t < TDIM; t++) {
        const float4* hin = reinterpret_cast<const float4*>(g_hbuf[t & 1]);
        float*        hout = g_hbuf[(t + 1) & 1];

        const float x0 = y_hist[(b0 + 0) * TDIM + t];
        const float x1 = y_hist[(b0 + 1) * TDIM + t];

        ull aif0 = pack2(fmaf(x0, wih_[0], bs_[0]), fmaf(x0, wih_[1], bs_[1]));
        ull ago0 = pack2(fmaf(x0, wih_[2], bs_[2]), fmaf(x0, wih_[3], bs_[3]));
        ull aif1 = pack2(fmaf(x1, wih_[0], bs_[0]), fmaf(x1, wih_[1], bs_[1]));
        ull ago1 = pack2(fmaf(x1, wih_[2], bs_[2]), fmaf(x1, wih_[3], bs_[3]));

#pragma unroll
        for (int ph = 0; ph < 2; ph++) {
            // ---- stage h[ph*512 .. +512) x 32 batches into smem, duplicated ----
#pragma unroll
            for (int i = 0; i < 8; i++) {
                int idx = tid + i * 512;          // 0..4095
                int kk  = idx >> 3;               // 0..511
                int q   = idx & 7;                // batch quad
                float4 v = __ldcg(&hin[(ph * KHALF + kk) * (BDIM / 4) + bg * 8 + q]);
                float4* d = reinterpret_cast<float4*>(&h_s[kk * 64 + q * 8]);
                d[0] = make_float4(v.x, v.x, v.y, v.y);
                d[1] = make_float4(v.z, v.z, v.w, v.w);
            }
            __syncthreads();

            const longlong2* wq = wbase + (size_t)(ph * KHALF) * (G4 / 4);
            const ull* hp = reinterpret_cast<const ull*>(h_s) + bloc;

#pragma unroll 8
            for (int kk = 0; kk < KHALF; kk++) {
                ull hd0 = hp[kk * 32];        // (h[k][b0], h[k][b0]) duplicated
                ull hd1 = hp[kk * 32 + 1];
                longlong2 wv = wq[(size_t)kk * (G4 / 4)];
                ffma2(aif0, hd0, (ull)wv.x);
                ffma2(ago0, hd0, (ull)wv.y);
                ffma2(aif1, hd1, (ull)wv.x);
                ffma2(ago1, hd1, (ull)wv.y);
            }
            __syncthreads();   // smem reused by next phase
        }

        // ---- gates + state update ----
        float iv, fv, gv, ov;
        unpack2(aif0, iv, fv); unpack2(ago0, gv, ov);
        {
            float ig = sigmoidf_(iv), fg = sigmoidf_(fv);
            float gg = tanhf(gv),     og = sigmoidf_(ov);
            c_[0] = fg * c_[0] + ig * gg;
            __stcg(&hout[j * BDIM + b0], og * tanhf(c_[0]));
        }
        unpack2(aif1, iv, fv); unpack2(ago1, gv, ov);
        {
            float ig = sigmoidf_(iv), fg = sigmoidf_(fv);
            float gg = tanhf(gv),     og = sigmoidf_(ov);
            c_[1] = fg * c_[1] + ig * gg;
            __stcg(&hout[j * BDIM + b0 + 1], og * tanhf(c_[1]));
        }

        grid_barrier((unsigned)(t + 1), nblk);
    }
    // final h lands in g_hbuf[0] (512 even)
}

// ---------------- final FC ----------------
__global__ void fc_kernel(const float* __restrict__ fc_W,
                          const float* __restrict__ fc_b,
                          float* __restrict__ out) {
    int b = blockIdx.x;
    int o = threadIdx.x;
    const float* h = g_hbuf[0];   // k-major [k][b]
    const float4* wp = reinterpret_cast<const float4*>(fc_W + o * HDIM);
    float s = 0.0f;
#pragma unroll 4
    for (int k = 0; k < HDIM; k += 4) {
        float4 w = wp[k >> 2];
        s += h[(k + 0) * BDIM + b] * w.x;
        s += h[(k + 1) * BDIM + b] * w.y;
        s += h[(k + 2) * BDIM + b] * w.z;
        s += h[(k + 3) * BDIM + b] * w.w;
    }
    out[b * ODIM + o] = s + fc_b[o];
}

// ---------------- launch ----------------
extern "C" void kernel_launch(void* const* d_in, const int* in_sizes, int n_in,
                              void* d_out, int out_size) {
    const float* y_hist = (const float*)d_in[0];
    const float* W_ih   = (const float*)d_in[1];
    const float* W_hh   = (const float*)d_in[2];
    const float* b_ih   = (const float*)d_in[3];
    const float* b_hh   = (const float*)d_in[4];
    const float* fc_W   = (const float*)d_in[5];
    const float* fc_b   = (const float*)d_in[6];
    const float* h0     = (const float*)d_in[7];
    const float* c0     = (const float*)d_in[8];
    float* out = (float*)d_out;

    const int smem_bytes = KHALF * 64 * sizeof(float);   // 128 KB
    // Idempotent, not a stream op — safe to call every time (no static state).
    cudaFuncSetAttribute(lstm_persistent,
                         cudaFuncAttributeMaxDynamicSharedMemorySize, smem_bytes);

    prep_w2<<<(HDIM * HDIM * 4 + 255) / 256, 256>>>(W_hh);
    prep_misc<<<(BDIM * HDIM + 255) / 256, 256>>>(b_ih, b_hh, h0);
    lstm_persistent<<<128, 512, smem_bytes>>>(y_hist, W_ih, c0);
    fc_kernel<<<BDIM, ODIM>>>(fc_W, fc_b, out);
}

// round 8
// speedup vs baseline: 1.5402x; 1.1151x over previous
#include <cuda_runtime.h>
#include <cstdint>

// Problem constants
#define BDIM 128     // batch
#define TDIM 512     // timesteps
#define HDIM 1024    // hidden
#define G4   4096    // 4*H gate rows
#define ODIM 128     // output
#define KHALF 512    // k-phase size (h smem staged in 2 halves)

typedef unsigned long long ull;

// ---------------- device scratch (no allocations allowed) ----------------
__device__ float g_hbuf[2][HDIM * BDIM];   // h state, k-major: [k][b], double buffered
__device__ float g_W2[HDIM * HDIM * 4];    // W_hh transposed: [k][j][gate(i,f,g,o)]
__device__ float g_bsum[G4];               // b_ih + b_hh
__device__ unsigned g_arrive;
__device__ volatile unsigned g_release;

// ---------------- f32x2 packed-FMA helpers (FFMA2, sm_10x) ----------------
__device__ __forceinline__ ull pack2(float a, float b) {
    ull r; asm("mov.b64 %0, {%1, %2};" : "=l"(r) : "f"(a), "f"(b)); return r;
}
__device__ __forceinline__ void unpack2(ull v, float& a, float& b) {
    asm("mov.b64 {%0, %1}, %2;" : "=f"(a), "=f"(b) : "l"(v));
}
__device__ __forceinline__ void ffma2(ull& d, ull a, ull b) {
    asm("fma.rn.f32x2 %0, %1, %2, %0;" : "+l"(d) : "l"(a), "l"(b));
}
__device__ __forceinline__ float sigmoidf_(float x) {
    return 1.0f / (1.0f + __expf(-x));
}

// ---------------- prep kernels ----------------
// W2[k*4096 + j*4 + g] = W_hh[(g*1024 + j)*1024 + k]
__global__ void prep_w2(const float* __restrict__ W_hh) {
    int idx = blockIdx.x * blockDim.x + threadIdx.x;
    if (idx < HDIM * HDIM * 4) {
        int g = idx & 3;
        int j = (idx >> 2) & (HDIM - 1);
        int k = idx >> 12;
        g_W2[idx] = W_hh[((g << 10) + j) * HDIM + k];
    }
}

__global__ void prep_misc(const float* __restrict__ b_ih,
                          const float* __restrict__ b_hh,
                          const float* __restrict__ h0) {
    int idx = blockIdx.x * blockDim.x + threadIdx.x;
    if (idx < G4) g_bsum[idx] = b_ih[idx] + b_hh[idx];
    if (idx < BDIM * HDIM) {
        int b = idx >> 10;
        int k = idx & (HDIM - 1);
        g_hbuf[0][k * BDIM + b] = h0[idx];
    }
    if (idx == 0) { g_arrive = 0u; g_release = 0u; }
}

// ---------------- grid-wide barrier (monotonic release) ----------------
// 128 CTAs, 1/SM (smem-limited), trivially co-resident on 148 SMs.
__device__ __forceinline__ void grid_barrier(unsigned want, unsigned nblk) {
    __syncthreads();
    if (threadIdx.x == 0) {
        __threadfence();  // publish h writes (CCTL.IVALL at gpu scope)
        unsigned t = atomicAdd(&g_arrive, 1u);
        if (t == nblk - 1u) {
            atomicExch(&g_arrive, 0u);
            __threadfence();
            g_release = want;
        } else {
            while (g_release < want) { }
            __threadfence();  // acquire + L1 invalidate
        }
    }
    __syncthreads();
}

// ---------------- persistent LSTM kernel ----------------
// Grid 128 = 32 j-groups x 4 batch-groups. Block 256 = 8 warps (2/SMSP).
// Warp w: batches bg*32 + w*4 .. +3 (nB=4 per thread). Lane: j = jb*32 + lane.
// nB=4 halves W-bytes-per-MAC vs R3: L1tex wavefronts 32K cyc/step, FMA 32K —
// both pipes at the wall, overlapped.
// Accumulators are gate pairs (i,f)/(g,o) per batch: W float4 [k][j][4] feeds
// two f32x2 operands directly. h staged in smem duplicated (h_b,h_b), two
// 512-k phases (128 KB).
__global__ void __launch_bounds__(256, 1)
lstm_persistent(const float* __restrict__ y_hist,   // [B][T]
                const float* __restrict__ W_ih,     // [4096]
                const float* __restrict__ c0)       // [B][H]
{
    extern __shared__ float h_s[];   // [KHALF][32 b][2 dup] floats = 128 KB

    const int tid  = threadIdx.x;
    const int lane = tid & 31;
    const int warp = tid >> 5;          // 0..7
    const int jb   = blockIdx.x & 31;
    const int bg   = blockIdx.x >> 5;   // 0..3
    const int j    = jb * 32 + lane;
    const int b0   = bg * 32 + warp * 4;   // this thread's 4 batches
    const unsigned nblk = gridDim.x;

    float wih_[4], bs_[4];
#pragma unroll
    for (int g = 0; g < 4; g++) {
        wih_[g] = W_ih[(g << 10) + j];
        bs_[g]  = g_bsum[(g << 10) + j];
    }
    float c_[4];
#pragma unroll
    for (int i = 0; i < 4; i++) c_[i] = c0[(b0 + i) * HDIM + j];

    // W row pointer: longlong2 per (k,j) = {(w_i,w_f),(w_g,w_o)}
    const longlong2* wbase = reinterpret_cast<const longlong2*>(g_W2) + j;

    for (int t = 0; t < TDIM; t++) {
        const float4* hin = reinterpret_cast<const float4*>(g_hbuf[t & 1]);
        float*        hout = g_hbuf[(t + 1) & 1];

        float x_[4];
#pragma unroll
        for (int i = 0; i < 4; i++) x_[i] = y_hist[(b0 + i) * TDIM + t];

        ull aif[4], ago[4];
#pragma unroll
        for (int i = 0; i < 4; i++) {
            aif[i] = pack2(fmaf(x_[i], wih_[0], bs_[0]), fmaf(x_[i], wih_[1], bs_[1]));
            ago[i] = pack2(fmaf(x_[i], wih_[2], bs_[2]), fmaf(x_[i], wih_[3], bs_[3]));
        }

#pragma unroll
        for (int ph = 0; ph < 2; ph++) {
            // ---- stage h[ph*512 .. +512) x 32 batches into smem, duplicated ----
#pragma unroll
            for (int i = 0; i < 16; i++) {
                int idx = tid + i * 256;          // 0..4095
                int kk  = idx >> 3;               // 0..511
                int q   = idx & 7;                // batch quad
                float4 v = __ldcg(&hin[(ph * KHALF + kk) * (BDIM / 4) + bg * 8 + q]);
                float4* d = reinterpret_cast<float4*>(&h_s[kk * 64 + q * 8]);
                d[0] = make_float4(v.x, v.x, v.y, v.y);
                d[1] = make_float4(v.z, v.z, v.w, v.w);
            }
            __syncthreads();

            const longlong2* wq = wbase + (size_t)(ph * KHALF) * (G4 / 4);
            // duplicated h pairs for this thread's 4 batches
            const ulonglong2* hp =
                reinterpret_cast<const ulonglong2*>(h_s) + warp * 2;

#pragma unroll 8
            for (int kk = 0; kk < KHALF; kk++) {
                ulonglong2 h01 = hp[kk * 16];       // (hb0,hb0),(hb1,hb1)
                ulonglong2 h23 = hp[kk * 16 + 1];   // (hb2,hb2),(hb3,hb3)
                longlong2 wv = wq[(size_t)kk * (G4 / 4)];
                ffma2(aif[0], h01.x, (ull)wv.x);
                ffma2(ago[0], h01.x, (ull)wv.y);
                ffma2(aif[1], h01.y, (ull)wv.x);
                ffma2(ago[1], h01.y, (ull)wv.y);
                ffma2(aif[2], h23.x, (ull)wv.x);
                ffma2(ago[2], h23.x, (ull)wv.y);
                ffma2(aif[3], h23.y, (ull)wv.x);
                ffma2(ago[3], h23.y, (ull)wv.y);
            }
            __syncthreads();   // smem reused by next phase
        }

        // ---- gates + state update, 4 batches ----
        float hn[4];
#pragma unroll
        for (int i = 0; i < 4; i++) {
            float iv, fv, gv, ov;
            unpack2(aif[i], iv, fv);
            unpack2(ago[i], gv, ov);
            float ig = sigmoidf_(iv), fg = sigmoidf_(fv);
            float gg = tanhf(gv),     og = sigmoidf_(ov);
            c_[i] = fg * c_[i] + ig * gg;
            hn[i] = og * tanhf(c_[i]);
        }
        // 4 consecutive batches -> one 16B store
        __stcg(reinterpret_cast<float4*>(&hout[j * BDIM + b0]),
               make_float4(hn[0], hn[1], hn[2], hn[3]));

        grid_barrier((unsigned)(t + 1), nblk);
    }
    // final h lands in g_hbuf[0] (512 even)
}

// ---------------- final FC ----------------
__global__ void fc_kernel(const float* __restrict__ fc_W,
                          const float* __restrict__ fc_b,
                          float* __restrict__ out) {
    int b = blockIdx.x;
    int o = threadIdx.x;
    const float* h = g_hbuf[0];   // k-major [k][b]
    const float4* wp = reinterpret_cast<const float4*>(fc_W + o * HDIM);
    float s = 0.0f;
#pragma unroll 4
    for (int k = 0; k < HDIM; k += 4) {
        float4 w = wp[k >> 2];
        s += h[(k + 0) * BDIM + b] * w.x;
        s += h[(k + 1) * BDIM + b] * w.y;
        s += h[(k + 2) * BDIM + b] * w.z;
        s += h[(k + 3) * BDIM + b] * w.w;
    }
    out[b * ODIM + o] = s + fc_b[o];
}

// ---------------- launch ----------------
extern "C" void kernel_launch(void* const* d_in, const int* in_sizes, int n_in,
                              void* d_out, int out_size) {
    const float* y_hist = (const float*)d_in[0];
    const float* W_ih   = (const float*)d_in[1];
    const float* W_hh   = (const float*)d_in[2];
    const float* b_ih   = (const float*)d_in[3];
    const float* b_hh   = (const float*)d_in[4];
    const float* fc_W   = (const float*)d_in[5];
    const float* fc_b   = (const float*)d_in[6];
    const float* h0     = (const float*)d_in[7];
    const float* c0     = (const float*)d_in[8];
    float* out = (float*)d_out;

    const int smem_bytes = KHALF * 64 * sizeof(float);   // 128 KB
    // Idempotent, not a stream op — safe during graph capture, no static state.
    cudaFuncSetAttribute(lstm_persistent,
                         cudaFuncAttributeMaxDynamicSharedMemorySize, smem_bytes);

    prep_w2<<<(HDIM * HDIM * 4 + 255) / 256, 256>>>(W_hh);
    prep_misc<<<(BDIM * HDIM + 255) / 256, 256>>>(b_ih, b_hh, h0);
    lstm_persistent<<<128, 256, smem_bytes>>>(y_hist, W_ih, c0);
    fc_kernel<<<BDIM, ODIM>>>(fc_W, fc_b, out);
}